// round 5
// baseline (speedup 1.0000x reference)
#include <cuda_runtime.h>
#include <math.h>

#define BB   256        // batch
#define OBSN 256
#define DIN  512
#define DDIM 1024
#define MMM  32
#define HIDN 16
#define NSYN 64
#define NITR 4
#define NSYNCH 2080     // 64*65/2

// ---------------- scratch (device globals; no runtime allocation) ----------------
__device__ float g_st[BB*MMM*DDIM];      // circular state trace, layout [b][m][d]
__device__ float g_at[BB*MMM*DDIM];      // circular activated trace, layout [b][m][d]
__device__ float g_f [BB*DIN];           // backbone features
__device__ float g_pre[BB*(DIN+DDIM)];   // synapse input
__device__ float g_tmp[BB*2048];         // GEMM outputs (pre-GLU)
__device__ float g_h [BB*DDIM];          // synapse hidden
__device__ unsigned char g_done[BB];     // decoded reset flags

__device__ __forceinline__ float sigmoidf(float x){ return 1.f/(1.f+expf(-x)); }

// ---------------- decode dones robustly (uint8 vs int32 vs float32 storage) ----------
// Uses only the first 256 bytes (valid under every candidate width).
//  - any byte > 1            -> float32 (1.0f has bytes 0x80, 0x3F)
//  - nonzero byte at off%4!=0 -> uint8 (true packed bools)
//  - otherwise               -> int32 (0/1 words: only byte0 can be nonzero)
__global__ void decode_dones(const unsigned char* __restrict__ p)
{
    __shared__ int has_gt1, has_off;
    int t = threadIdx.x;
    if (t == 0){ has_gt1 = 0; has_off = 0; }
    __syncthreads();
    unsigned char v = p[t];
    if (v > 1)               atomicOr(&has_gt1, 1);
    if (v != 0 && (t & 3))   atomicOr(&has_off, 1);
    __syncthreads();
    bool d;
    if (has_gt1)      d = ((const float*)p)[t] != 0.0f;
    else if (has_off) d = p[t] != 0;
    else              d = ((const int*)p)[t] != 0;
    g_done[t] = d ? 1 : 0;
}

// ---------------- init: apply dones reset, transpose (B,D,M) -> [b][m][d] ----------------
__global__ void init_state(const float* __restrict__ st_in, const float* __restrict__ at_in,
                           const float* __restrict__ st0,   const float* __restrict__ at0)
{
    int idx = blockIdx.x*blockDim.x + threadIdx.x;
    if (idx >= BB*MMM*DDIM) return;
    int b = idx / (MMM*DDIM);
    int r = idx - b*MMM*DDIM;
    int m = r / DDIM;
    int d = r - m*DDIM;
    bool rs = g_done[b] != 0;
    g_st[idx] = rs ? st0[d*MMM+m] : st_in[(b*DDIM+d)*MMM+m];
    g_at[idx] = rs ? at0[d*MMM+m] : at_in[(b*DDIM+d)*MMM+m];
}

// ---------------- SGEMM: C[M,N] = A[M,K] @ W[K,N] + bias (fp32) ----------------
// BM=BN=64, BK=16, 256 threads, 4x4 microtile. All dims divide evenly for this problem.
__global__ __launch_bounds__(256) void sgemm_bias(
    const float* __restrict__ A, const float* __restrict__ W,
    const float* __restrict__ bias, float* __restrict__ C, int N, int K)
{
    __shared__ float As[16][68];   // [k][m], padded
    __shared__ float Bs[16][64];   // [k][n]
    int tid = threadIdx.x;
    int tx = tid & 15, ty = tid >> 4;
    int m0 = blockIdx.y*64, n0 = blockIdx.x*64;
    int ar = tid >> 2,  ac = (tid & 3)*4;
    int br = tid >> 4,  bc = (tid & 15)*4;

    float acc[4][4];
    #pragma unroll
    for (int i=0;i<4;i++)
        #pragma unroll
        for (int j=0;j<4;j++) acc[i][j]=0.f;

    for (int k0=0; k0<K; k0+=16){
        float4 av = *(const float4*)(A + (m0+ar)*K + k0 + ac);
        As[ac+0][ar]=av.x; As[ac+1][ar]=av.y; As[ac+2][ar]=av.z; As[ac+3][ar]=av.w;
        float4 bv = *(const float4*)(W + (k0+br)*N + n0 + bc);
        *(float4*)&Bs[br][bc] = bv;
        __syncthreads();
        #pragma unroll
        for (int kk=0; kk<16; kk++){
            float a_[4];
            #pragma unroll
            for (int i=0;i<4;i++) a_[i]=As[kk][ty*4+i];
            float4 b4 = *(float4*)&Bs[kk][tx*4];
            float b_[4] = {b4.x,b4.y,b4.z,b4.w};
            #pragma unroll
            for (int i=0;i<4;i++)
                #pragma unroll
                for (int j=0;j<4;j++) acc[i][j] += a_[i]*b_[j];
        }
        __syncthreads();
    }
    float4 bi = *(const float4*)(bias + n0 + tx*4);
    #pragma unroll
    for (int i=0;i<4;i++){
        float4 o;
        o.x=acc[i][0]+bi.x; o.y=acc[i][1]+bi.y; o.z=acc[i][2]+bi.z; o.w=acc[i][3]+bi.w;
        *(float4*)(C + (m0+ty*4+i)*N + n0 + tx*4) = o;
    }
}

// ---------------- GLU + LayerNorm: in X[b, 2N] -> out[b*ostride + j], j<N ----------------
__global__ __launch_bounds__(256) void glu_ln(
    const float* __restrict__ X, const float* __restrict__ gamma,
    const float* __restrict__ beta, float* __restrict__ outp, int N, int ostride)
{
    __shared__ float sg[1024];
    __shared__ float red[18];
    int b = blockIdx.x, t = threadIdx.x;
    const float* xr = X + b*2*N;
    float s1=0.f, s2=0.f;
    for (int j=t; j<N; j+=256){
        float a = xr[j];
        float g = a * sigmoidf(xr[N+j]);
        sg[j]=g; s1+=g; s2+=g*g;
    }
    #pragma unroll
    for (int o=16;o;o>>=1){ s1+=__shfl_xor_sync(0xffffffffu,s1,o); s2+=__shfl_xor_sync(0xffffffffu,s2,o); }
    if ((t&31)==0){ red[t>>5]=s1; red[8+(t>>5)]=s2; }
    __syncthreads();
    if (t==0){
        float a=0.f,c=0.f;
        for (int i=0;i<8;i++){ a+=red[i]; c+=red[8+i]; }
        red[16]=a; red[17]=c;
    }
    __syncthreads();
    float mu  = red[16]/(float)N;
    float var = red[17]/(float)N - mu*mu;
    float inv = rsqrtf(var + 1e-6f);
    for (int j=t; j<N; j+=256)
        outp[b*ostride + j] = (sg[j]-mu)*inv*gamma[j] + beta[j];
}

// ---------------- assemble pre = concat(f, at[:,:,last]) ----------------
__global__ void assemble_pre(int lastphys)
{
    int idx = blockIdx.x*blockDim.x + threadIdx.x;
    if (idx >= BB*(DIN+DDIM)) return;
    int b = idx / (DIN+DDIM), j = idx - b*(DIN+DDIM);
    g_pre[idx] = (j < DIN) ? g_f[b*DIN+j]
                           : g_at[(b*MMM+lastphys)*DDIM + (j-DIN)];
}

// ---------------- NLM: per-(b,d) 32->32 GLU MLP -> 16->2 GLU -> scalar ----------------
// Block: 32 batches x 4 d's, 128 threads, weights+state staged in smem.
__global__ __launch_bounds__(128) void nlm_kernel(
    const float* __restrict__ w1, const float* __restrict__ b1, const float* __restrict__ T1,
    const float* __restrict__ w2, const float* __restrict__ b2, const float* __restrict__ T2,
    int base, int slot)
{
    __shared__ float W1s[32*32*4];   // [(m*32+h)*4 + dd]
    __shared__ float STs[32*32*4];   // [m*128 + bb*4 + dd]
    __shared__ float B1s[32*4];      // [h*4+dd]
    __shared__ float W2s[32*4];      // [(k*2+j)*4+dd]
    __shared__ float B2s[8];         // [j*4+dd]
    int t = threadIdx.x;
    int d0 = blockIdx.x*4, b0 = blockIdx.y*32;

    #pragma unroll
    for (int i=0;i<8;i++){
        int idx = t + i*128;                          // 0..1023
        float4 v = *(const float4*)(w1 + idx*DDIM + d0);
        *(float4*)&W1s[idx*4] = v;
        int bb = idx >> 5, m = idx & 31;
        int phys = (base + m) & 31;
        float4 s = *(const float4*)(g_st + ((size_t)(b0+bb)*MMM + phys)*DDIM + d0);
        *(float4*)&STs[(m*32+bb)*4] = s;
    }
    { int h = t>>2, dd = t&3; B1s[t] = b1[(d0+dd)*32 + h]; }
    { int kj = t>>2, dd = t&3; W2s[t] = w2[kj*DDIM + d0 + dd]; }
    if (t < 8){ int j = t>>2, dd = t&3; B2s[t] = b2[(d0+dd)*2 + j]; }
    __syncthreads();

    float invT1 = 1.0f/T1[0], invT2 = 1.0f/T2[0];
    int dd = t & 3;
    int bb = t >> 2;

    float str[32];
    #pragma unroll
    for (int m=0;m<32;m++) str[m] = STs[m*128 + t];

    float x[32];
    #pragma unroll
    for (int h=0;h<32;h++){
        float acc = B1s[h*4+dd];
        #pragma unroll
        for (int m=0;m<32;m++) acc += str[m]*W1s[(m*32+h)*4+dd];
        x[h] = acc*invT1;
    }
    float y0 = B2s[dd], y1 = B2s[4+dd];
    #pragma unroll
    for (int k=0;k<16;k++){
        float g = x[k] * sigmoidf(x[k+16]);
        y0 += g*W2s[(k*2+0)*4+dd];
        y1 += g*W2s[(k*2+1)*4+dd];
    }
    y0 *= invT2; y1 *= invT2;
    float outv = y0 * sigmoidf(y1);
    g_at[((size_t)(b0+bb)*MMM + slot)*DDIM + d0 + dd] = outv;
}

// ---------------- synchronization output ----------------
__global__ __launch_bounds__(256) void synch_kernel(
    const float* __restrict__ dp, float* __restrict__ outp, int base)
{
    __shared__ float S[32][64];
    int b = blockIdx.x, t = threadIdx.x;
    #pragma unroll
    for (int i=0;i<8;i++){
        int idx = t + i*256; int m = idx >> 6, n = idx & 63;
        S[m][n] = g_at[((size_t)b*MMM + ((base+m)&31))*DDIM + (DDIM-NSYN) + n];
    }
    __syncthreads();
    for (int p=t; p<NSYNCH; p+=256){
        int i=0, off=0;
        while (p >= off + (NSYN - i)){ off += NSYN - i; ++i; }
        int j = i + (p - off);
        float c = fminf(fmaxf(dp[p], 0.f), 4.f);
        float num=0.f, den=0.f;
        #pragma unroll
        for (int m=0;m<32;m++){
            float w = expf(-(float)(31-m)*c);
            den += w;
            num += w * S[m][i]*S[m][j];
        }
        outp[b*NSYNCH + p] = num / sqrtf(den);
    }
}

// ---------------- final transpose [b][m][d] -> (B,D,M) output layout ----------------
__global__ void transpose_out(float* __restrict__ outp, int base)
{
    __shared__ float tile[32][33];
    const float* src = blockIdx.z ? g_at : g_st;
    float* dst = outp + (size_t)blockIdx.z * (size_t)BB*DDIM*MMM;
    int b = blockIdx.y, d0 = blockIdx.x*32, t = threadIdx.x;
    #pragma unroll
    for (int i=0;i<4;i++){
        int idx = t + i*256; int m = idx >> 5, dd = idx & 31;
        tile[m][dd] = src[((size_t)b*MMM + ((base+m)&31))*DDIM + d0 + dd];
    }
    __syncthreads();
    #pragma unroll
    for (int i=0;i<4;i++){
        int idx = t + i*256; int dd = idx >> 5, m = idx & 31;
        dst[((size_t)b*DDIM + d0 + dd)*MMM + m] = tile[m][dd];
    }
}

// ---------------- host launch ----------------
extern "C" void kernel_launch(void* const* d_in, const int* in_sizes, int n_in,
                              void* d_out, int out_size)
{
    const float* obs          = (const float*)d_in[0];
    const unsigned char* dones= (const unsigned char*)d_in[1];
    // d_in[2] avail_actions: unused
    const float* state_trace  = (const float*)d_in[3];
    const float* at_trace     = (const float*)d_in[4];
    const float* start_trace  = (const float*)d_in[5];
    const float* start_at     = (const float*)d_in[6];
    const float* bb_w1  = (const float*)d_in[7];
    const float* bb_b1  = (const float*)d_in[8];
    const float* bb_l1s = (const float*)d_in[9];
    const float* bb_l1b = (const float*)d_in[10];
    const float* bb_w2  = (const float*)d_in[11];
    const float* bb_b2  = (const float*)d_in[12];
    const float* bb_l2s = (const float*)d_in[13];
    const float* bb_l2b = (const float*)d_in[14];
    const float* syn_w1 = (const float*)d_in[15];
    const float* syn_b1 = (const float*)d_in[16];
    const float* syn_l1s= (const float*)d_in[17];
    const float* syn_l1b= (const float*)d_in[18];
    const float* syn_w2 = (const float*)d_in[19];
    const float* syn_b2 = (const float*)d_in[20];
    const float* syn_l2s= (const float*)d_in[21];
    const float* syn_l2b= (const float*)d_in[22];
    const float* nlm1_w = (const float*)d_in[23];
    const float* nlm1_b = (const float*)d_in[24];
    const float* nlm1_T = (const float*)d_in[25];
    const float* nlm2_w = (const float*)d_in[26];
    const float* nlm2_b = (const float*)d_in[27];
    const float* nlm2_T = (const float*)d_in[28];
    const float* decayp = (const float*)d_in[29];
    float* outp = (float*)d_out;

    float *p_f, *p_pre, *p_tmp, *p_h, *p_st;
    cudaGetSymbolAddress((void**)&p_f,   g_f);
    cudaGetSymbolAddress((void**)&p_pre, g_pre);
    cudaGetSymbolAddress((void**)&p_tmp, g_tmp);
    cudaGetSymbolAddress((void**)&p_h,   g_h);
    cudaGetSymbolAddress((void**)&p_st,  g_st);

    // 1) decode reset flags + relayout state traces
    decode_dones<<<1, BB>>>(dones);
    init_state<<<(BB*MMM*DDIM + 255)/256, 256>>>(state_trace, at_trace, start_trace, start_at);

    // 2) backbone: 2x (GEMM -> GLU+LN)
    sgemm_bias<<<dim3(1024/64, BB/64), 256>>>(obs, bb_w1, bb_b1, p_tmp, 1024, OBSN);
    glu_ln<<<BB, 256>>>(p_tmp, bb_l1s, bb_l1b, p_f, DIN, DIN);
    sgemm_bias<<<dim3(1024/64, BB/64), 256>>>(p_f, bb_w2, bb_b2, p_tmp, 1024, DIN);
    glu_ln<<<BB, 256>>>(p_tmp, bb_l2s, bb_l2b, p_f, DIN, DIN);

    // 3) recurrent iterations
    for (int t = 0; t < NITR; t++){
        int lastphys = (t + 31) & 31;
        assemble_pre<<<(BB*(DIN+DDIM) + 255)/256, 256>>>(lastphys);
        sgemm_bias<<<dim3(2048/64, BB/64), 256>>>(p_pre, syn_w1, syn_b1, p_tmp, 2048, DIN+DDIM);
        glu_ln<<<BB, 256>>>(p_tmp, syn_l1s, syn_l1b, p_h, DDIM, DDIM);
        sgemm_bias<<<dim3(2048/64, BB/64), 256>>>(p_h, syn_w2, syn_b2, p_tmp, 2048, DDIM);
        // write h2 directly into circular st slot t  (st shift-append)
        glu_ln<<<BB, 256>>>(p_tmp, syn_l2s, syn_l2b, p_st + (size_t)t*DDIM, DDIM, MMM*DDIM);
        // NLM reads new st (base t+1), writes new at slot t (at shift-append)
        nlm_kernel<<<dim3(DDIM/4, BB/32), 128>>>(nlm1_w, nlm1_b, nlm1_T,
                                                 nlm2_w, nlm2_b, nlm2_T,
                                                 (t + 1) & 31, t);
    }

    // 4) outputs
    synch_kernel<<<BB, 256>>>(decayp, outp + (size_t)2*BB*DDIM*MMM, NITR & 31);
    transpose_out<<<dim3(DDIM/32, BB, 2), 256>>>(outp, NITR & 31);
}

// round 7
// speedup vs baseline: 1.3482x; 1.3482x over previous
#include <cuda_runtime.h>
#include <math.h>

#define BB   256        // batch
#define OBSN 256
#define DIN  512
#define DDIM 1024
#define MMM  32
#define HIDN 16
#define NSYN 64
#define NITR 4
#define NSYNCH 2080     // 64*65/2

// ---------------- scratch (device globals; no runtime allocation) ----------------
__device__ float g_st[BB*MMM*DDIM];      // circular state trace, layout [b][m][d]
__device__ float g_at[BB*MMM*DDIM];      // circular activated trace, layout [b][m][d]
__device__ float g_f [BB*DIN];           // backbone features
__device__ float g_tmp[BB*2048];         // GEMM outputs (pre-GLU)
__device__ float g_h [BB*DDIM];          // synapse hidden
__device__ float g_r[NSYNCH];            // per-pair decay ratio
__device__ float g_invden[NSYNCH];       // per-pair 1/sqrt(den)
__device__ unsigned char g_done[BB];     // decoded reset flags

__device__ __forceinline__ float fsig(float x){
    return __fdividef(1.f, 1.f + __expf(-x));
}

// ---------------- tf32 helpers ----------------
__device__ __forceinline__ unsigned f2tf32(float x){
    unsigned r; asm("cvt.rna.tf32.f32 %0, %1;" : "=r"(r) : "f"(x)); return r;
}
__device__ __forceinline__ void split_tf32(float x, unsigned &hi, unsigned &lo){
    hi = f2tf32(x);
    lo = f2tf32(x - __uint_as_float(hi));
}
__device__ __forceinline__ void mma8(float* c, const unsigned* a, const unsigned* b){
    asm volatile("mma.sync.aligned.m16n8k8.row.col.f32.tf32.tf32.f32 "
        "{%0,%1,%2,%3}, {%4,%5,%6,%7}, {%8,%9}, {%0,%1,%2,%3};"
        : "+f"(c[0]), "+f"(c[1]), "+f"(c[2]), "+f"(c[3])
        : "r"(a[0]), "r"(a[1]), "r"(a[2]), "r"(a[3]), "r"(b[0]), "r"(b[1]));
}

// ---------------- decode dones robustly (uint8 vs int32 vs float32 storage) ----------
__global__ void decode_dones(const unsigned char* __restrict__ p)
{
    __shared__ int has_gt1, has_off;
    int t = threadIdx.x;
    if (t == 0){ has_gt1 = 0; has_off = 0; }
    __syncthreads();
    unsigned char v = p[t];
    if (v > 1)               atomicOr(&has_gt1, 1);
    if (v != 0 && (t & 3))   atomicOr(&has_off, 1);
    __syncthreads();
    bool d;
    if (has_gt1)      d = ((const float*)p)[t] != 0.0f;
    else if (has_off) d = p[t] != 0;
    else              d = ((const int*)p)[t] != 0;
    g_done[t] = d ? 1 : 0;
}

// ---------------- init: reset + transpose (B,D,M) -> [b][m][d], fully coalesced ----------
__global__ __launch_bounds__(256) void init_state(
    const float* __restrict__ st_in, const float* __restrict__ at_in,
    const float* __restrict__ st0,   const float* __restrict__ at0)
{
    __shared__ float ts[32][33], ta[32][33];
    int b = blockIdx.y, d0 = blockIdx.x*32, t = threadIdx.x;
    bool rs = g_done[b] != 0;
    #pragma unroll
    for (int i=0;i<4;i++){
        int idx = t + i*256; int dd = idx >> 5, m = idx & 31;
        int gidx = (d0+dd)*MMM + m;
        ts[dd][m] = rs ? st0[gidx] : st_in[(size_t)b*DDIM*MMM + gidx];
        ta[dd][m] = rs ? at0[gidx] : at_in[(size_t)b*DDIM*MMM + gidx];
    }
    __syncthreads();
    #pragma unroll
    for (int i=0;i<4;i++){
        int idx = t + i*256; int m = idx >> 5, dd = idx & 31;
        size_t o = ((size_t)b*MMM + m)*DDIM + d0 + dd;
        g_st[o] = ts[dd][m];
        g_at[o] = ta[dd][m];
    }
}

// ---------------- 3xTF32 tensor-core GEMM ----------------
// C[256,N] = concat-A[256,K] @ W[K,N] + bias.
// A element (r,k) = k<K1 ? A1[r*lda1+k] : A2[r*lda2+(k-K1)]  (fuses the pre-concat).
// BM=BN=64, BK=16, 256 threads = 8 warps in 2(m)x4(n), warp tile 32x16.
__global__ __launch_bounds__(256) void sgemm_tf32(
    const float* __restrict__ A1, int lda1,
    const float* __restrict__ A2, int lda2, int K1,
    const float* __restrict__ W, const float* __restrict__ bias,
    float* __restrict__ C, int N, int K)
{
    __shared__ float As[2][64][20];   // [m][k], stride 20 -> conflict-free frags
    __shared__ float Bs[2][16][72];   // [k][n], stride 72 -> conflict-free frags
    int tid = threadIdx.x;
    int m0 = blockIdx.y*64, n0 = blockIdx.x*64;
    int wid = tid >> 5, lane = tid & 31;
    int wm = wid >> 2, wn = wid & 3;        // warp tile origin: (wm*32, wn*16)
    int g = lane >> 2, t = lane & 3;

    int arow = tid >> 2, akq = (tid & 3)*4;   // A loader: row 0..63, k quad
    int brow = tid >> 4, bnq = (tid & 15)*4;  // B loader: k row 0..15, n quad

    float acc[2][2][4];
    #pragma unroll
    for (int a=0;a<2;a++)
        #pragma unroll
        for (int b=0;b<2;b++)
            #pragma unroll
            for (int c=0;c<4;c++) acc[a][b][c]=0.f;

    int KT = K >> 4;

    // preload tile 0
    {
        const float* asrc = (0 < K1 || K1==0) && (0 < K1)
            ? (A1 + (m0+arow)*lda1 + akq)
            : (A2 + (m0+arow)*lda2 + akq);
        // k0 = 0 always < K1 when K1>0; K1==K normally.
        asrc = (0 < K1) ? (A1 + (m0+arow)*lda1 + akq) : asrc;
        float4 av = *(const float4*)asrc;
        *(float4*)&As[0][arow][akq] = av;
        float4 bv = *(const float4*)(W + brow*N + n0 + bnq);
        *(float4*)&Bs[0][brow][bnq] = bv;
    }
    __syncthreads();

    for (int kt=0; kt<KT; kt++){
        int buf = kt & 1;
        float4 av, bv;
        bool more = (kt+1 < KT);
        if (more){
            int k0 = (kt+1) << 4;
            const float* asrc = (k0 < K1) ? (A1 + (m0+arow)*lda1 + k0 + akq)
                                          : (A2 + (m0+arow)*lda2 + (k0-K1) + akq);
            av = *(const float4*)asrc;
            bv = *(const float4*)(W + (k0+brow)*N + n0 + bnq);
        }

        #pragma unroll
        for (int k8=0;k8<2;k8++){
            int kb = k8*8;
            unsigned ah[2][4], al[2][4];
            #pragma unroll
            for (int mt=0;mt<2;mt++){
                int r = wm*32 + mt*16;
                float a0 = As[buf][r+g  ][kb+t];
                float a1 = As[buf][r+g+8][kb+t];
                float a2 = As[buf][r+g  ][kb+t+4];
                float a3 = As[buf][r+g+8][kb+t+4];
                split_tf32(a0, ah[mt][0], al[mt][0]);
                split_tf32(a1, ah[mt][1], al[mt][1]);
                split_tf32(a2, ah[mt][2], al[mt][2]);
                split_tf32(a3, ah[mt][3], al[mt][3]);
            }
            unsigned bh[2][2], bl[2][2];
            #pragma unroll
            for (int nt=0;nt<2;nt++){
                int c = wn*16 + nt*8 + g;
                float b0 = Bs[buf][kb+t  ][c];
                float b1 = Bs[buf][kb+t+4][c];
                split_tf32(b0, bh[nt][0], bl[nt][0]);
                split_tf32(b1, bh[nt][1], bl[nt][1]);
            }
            #pragma unroll
            for (int mt=0;mt<2;mt++)
                #pragma unroll
                for (int nt=0;nt<2;nt++){
                    mma8(acc[mt][nt], ah[mt], bh[nt]);
                    mma8(acc[mt][nt], al[mt], bh[nt]);
                    mma8(acc[mt][nt], ah[mt], bl[nt]);
                }
        }

        if (more){
            *(float4*)&As[buf^1][arow][akq] = av;
            *(float4*)&Bs[buf^1][brow][bnq] = bv;
            __syncthreads();
        }
    }

    // epilogue: bias + store
    #pragma unroll
    for (int mt=0;mt<2;mt++){
        #pragma unroll
        for (int nt=0;nt<2;nt++){
            int row = m0 + wm*32 + mt*16 + g;
            int col = n0 + wn*16 + nt*8 + 2*t;
            float bx = __ldg(bias + col), by = __ldg(bias + col + 1);
            float2 v0 = make_float2(acc[mt][nt][0]+bx, acc[mt][nt][1]+by);
            float2 v1 = make_float2(acc[mt][nt][2]+bx, acc[mt][nt][3]+by);
            *(float2*)&C[(size_t)row*N + col]     = v0;
            *(float2*)&C[(size_t)(row+8)*N + col] = v1;
        }
    }
}

// ---------------- GLU + LayerNorm ----------------
__global__ __launch_bounds__(256) void glu_ln(
    const float* __restrict__ X, const float* __restrict__ gamma,
    const float* __restrict__ beta, float* __restrict__ outp, int N, int ostride)
{
    __shared__ float sg[1024];
    __shared__ float red[18];
    int b = blockIdx.x, t = threadIdx.x;
    const float* xr = X + (size_t)b*2*N;
    float s1=0.f, s2=0.f;
    for (int j=t; j<N; j+=256){
        float a = xr[j];
        float gl = a * fsig(xr[N+j]);
        sg[j]=gl; s1+=gl; s2+=gl*gl;
    }
    #pragma unroll
    for (int o=16;o;o>>=1){ s1+=__shfl_xor_sync(0xffffffffu,s1,o); s2+=__shfl_xor_sync(0xffffffffu,s2,o); }
    if ((t&31)==0){ red[t>>5]=s1; red[8+(t>>5)]=s2; }
    __syncthreads();
    if (t==0){
        float a=0.f,c=0.f;
        for (int i=0;i<8;i++){ a+=red[i]; c+=red[8+i]; }
        red[16]=a; red[17]=c;
    }
    __syncthreads();
    float mu  = red[16]/(float)N;
    float var = red[17]/(float)N - mu*mu;
    float inv = rsqrtf(var + 1e-6f);
    for (int j=t; j<N; j+=256)
        outp[(size_t)b*ostride + j] = (sg[j]-mu)*inv*gamma[j] + beta[j];
}

// ---------------- NLM: per-(b,d) 32->32 GLU MLP -> 16->2 GLU -> scalar ----------------
__global__ __launch_bounds__(128) void nlm_kernel(
    const float* __restrict__ w1, const float* __restrict__ b1, const float* __restrict__ T1,
    const float* __restrict__ w2, const float* __restrict__ b2, const float* __restrict__ T2,
    int base, int slot)
{
    __shared__ float W1s[32*32*4];
    __shared__ float STs[32*32*4];
    __shared__ float B1s[32*4];
    __shared__ float W2s[32*4];
    __shared__ float B2s[8];
    int t = threadIdx.x;
    int d0 = blockIdx.x*4, b0 = blockIdx.y*32;

    #pragma unroll
    for (int i=0;i<8;i++){
        int idx = t + i*128;
        float4 v = *(const float4*)(w1 + (size_t)idx*DDIM + d0);
        *(float4*)&W1s[idx*4] = v;
        int bb = idx >> 5, m = idx & 31;
        int phys = (base + m) & 31;
        float4 s = *(const float4*)(g_st + ((size_t)(b0+bb)*MMM + phys)*DDIM + d0);
        *(float4*)&STs[(m*32+bb)*4] = s;
    }
    { int h = t>>2, dd = t&3; B1s[t] = b1[(d0+dd)*32 + h]; }
    { int kj = t>>2, dd = t&3; W2s[t] = w2[(size_t)kj*DDIM + d0 + dd]; }
    if (t < 8){ int j = t>>2, dd = t&3; B2s[t] = b2[(d0+dd)*2 + j]; }
    __syncthreads();

    float invT1 = 1.0f/T1[0], invT2 = 1.0f/T2[0];
    int dd = t & 3;
    int bb = t >> 2;

    float str[32];
    #pragma unroll
    for (int m=0;m<32;m++) str[m] = STs[m*128 + t];

    float x[32];
    #pragma unroll
    for (int h=0;h<32;h++){
        float acc = B1s[h*4+dd];
        #pragma unroll
        for (int m=0;m<32;m++) acc += str[m]*W1s[(m*32+h)*4+dd];
        x[h] = acc*invT1;
    }
    float y0 = B2s[dd], y1 = B2s[4+dd];
    #pragma unroll
    for (int k=0;k<16;k++){
        float gl = x[k] * fsig(x[k+16]);
        y0 += gl*W2s[(k*2+0)*4+dd];
        y1 += gl*W2s[(k*2+1)*4+dd];
    }
    y0 *= invT2; y1 *= invT2;
    float outv = y0 * fsig(y1);
    g_at[((size_t)(b0+bb)*MMM + slot)*DDIM + d0 + dd] = outv;
}

// ---------------- synch precompute: r[p], 1/sqrt(den[p]) ----------------
__global__ void synch_prep(const float* __restrict__ dp)
{
    int p = blockIdx.x*256 + threadIdx.x;
    if (p >= NSYNCH) return;
    float c = fminf(fmaxf(dp[p], 0.f), 4.f);
    float r = __expf(-c);
    float den = 1.f, rp = 1.f;
    #pragma unroll
    for (int k=1;k<32;k++){ rp *= r; den += rp; }
    g_r[p] = r;
    g_invden[p] = rsqrtf(den);
}

// ---------------- synchronization output (Horner, no exp) ----------------
__global__ __launch_bounds__(256) void synch_kernel(float* __restrict__ outp, int base)
{
    __shared__ float S[32][64];
    int b = blockIdx.x, t = threadIdx.x;
    #pragma unroll
    for (int i=0;i<8;i++){
        int idx = t + i*256; int m = idx >> 6, n = idx & 63;
        S[m][n] = g_at[((size_t)b*MMM + ((base+m)&31))*DDIM + (DDIM-NSYN) + n];
    }
    __syncthreads();
    for (int p=t; p<NSYNCH; p+=256){
        int i=0, off=0;
        while (p >= off + (NSYN - i)){ off += NSYN - i; ++i; }
        int j = i + (p - off);
        float r = g_r[p];
        float num = 0.f;
        #pragma unroll
        for (int m=0;m<32;m++)
            num = num*r + S[m][i]*S[m][j];
        outp[(size_t)b*NSYNCH + p] = num * g_invden[p];
    }
}

// ---------------- final transpose [b][m][d] -> (B,D,M) output layout ----------------
__global__ void transpose_out(float* __restrict__ outp, int base)
{
    __shared__ float tile[32][33];
    const float* src = blockIdx.z ? g_at : g_st;
    float* dst = outp + (size_t)blockIdx.z * (size_t)BB*DDIM*MMM;
    int b = blockIdx.y, d0 = blockIdx.x*32, t = threadIdx.x;
    #pragma unroll
    for (int i=0;i<4;i++){
        int idx = t + i*256; int m = idx >> 5, dd = idx & 31;
        tile[m][dd] = src[((size_t)b*MMM + ((base+m)&31))*DDIM + d0 + dd];
    }
    __syncthreads();
    #pragma unroll
    for (int i=0;i<4;i++){
        int idx = t + i*256; int dd = idx >> 5, m = idx & 31;
        dst[((size_t)b*DDIM + d0 + dd)*MMM + m] = tile[m][dd];
    }
}

// ---------------- host launch ----------------
extern "C" void kernel_launch(void* const* d_in, const int* in_sizes, int n_in,
                              void* d_out, int out_size)
{
    const float* obs          = (const float*)d_in[0];
    const unsigned char* dones= (const unsigned char*)d_in[1];
    const float* state_trace  = (const float*)d_in[3];
    const float* at_trace     = (const float*)d_in[4];
    const float* start_trace  = (const float*)d_in[5];
    const float* start_at     = (const float*)d_in[6];
    const float* bb_w1  = (const float*)d_in[7];
    const float* bb_b1  = (const float*)d_in[8];
    const float* bb_l1s = (const float*)d_in[9];
    const float* bb_l1b = (const float*)d_in[10];
    const float* bb_w2  = (const float*)d_in[11];
    const float* bb_b2  = (const float*)d_in[12];
    const float* bb_l2s = (const float*)d_in[13];
    const float* bb_l2b = (const float*)d_in[14];
    const float* syn_w1 = (const float*)d_in[15];
    const float* syn_b1 = (const float*)d_in[16];
    const float* syn_l1s= (const float*)d_in[17];
    const float* syn_l1b= (const float*)d_in[18];
    const float* syn_w2 = (const float*)d_in[19];
    const float* syn_b2 = (const float*)d_in[20];
    const float* syn_l2s= (const float*)d_in[21];
    const float* syn_l2b= (const float*)d_in[22];
    const float* nlm1_w = (const float*)d_in[23];
    const float* nlm1_b = (const float*)d_in[24];
    const float* nlm1_T = (const float*)d_in[25];
    const float* nlm2_w = (const float*)d_in[26];
    const float* nlm2_b = (const float*)d_in[27];
    const float* nlm2_T = (const float*)d_in[28];
    const float* decayp = (const float*)d_in[29];
    float* outp = (float*)d_out;

    float *p_f, *p_tmp, *p_h, *p_st, *p_at;
    cudaGetSymbolAddress((void**)&p_f,   g_f);
    cudaGetSymbolAddress((void**)&p_tmp, g_tmp);
    cudaGetSymbolAddress((void**)&p_h,   g_h);
    cudaGetSymbolAddress((void**)&p_st,  g_st);
    cudaGetSymbolAddress((void**)&p_at,  g_at);

    // 1) decode reset flags + relayout state traces + synch prefactors
    decode_dones<<<1, BB>>>(dones);
    init_state<<<dim3(DDIM/32, BB), 256>>>(state_trace, at_trace, start_trace, start_at);
    synch_prep<<<(NSYNCH+255)/256, 256>>>(decayp);

    // 2) backbone: 2x (GEMM -> GLU+LN)
    sgemm_tf32<<<dim3(1024/64, 4), 256>>>(obs, OBSN, (const float*)0, 0, OBSN,
                                          bb_w1, bb_b1, p_tmp, 1024, OBSN);
    glu_ln<<<BB, 256>>>(p_tmp, bb_l1s, bb_l1b, p_f, DIN, DIN);
    sgemm_tf32<<<dim3(1024/64, 4), 256>>>(p_f, DIN, (const float*)0, 0, DIN,
                                          bb_w2, bb_b2, p_tmp, 1024, DIN);
    glu_ln<<<BB, 256>>>(p_tmp, bb_l2s, bb_l2b, p_f, DIN, DIN);

    // 3) recurrent iterations
    for (int t = 0; t < NITR; t++){
        int lastphys = (t + 31) & 31;
        // syn1: A = concat(f, at[:, :, last])  (concat fused into GEMM A-loader)
        sgemm_tf32<<<dim3(2048/64, 4), 256>>>(p_f, DIN,
                                              p_at + (size_t)lastphys*DDIM, MMM*DDIM, DIN,
                                              syn_w1, syn_b1, p_tmp, 2048, DIN+DDIM);
        glu_ln<<<BB, 256>>>(p_tmp, syn_l1s, syn_l1b, p_h, DDIM, DDIM);
        sgemm_tf32<<<dim3(2048/64, 4), 256>>>(p_h, DDIM, (const float*)0, 0, DDIM,
                                              syn_w2, syn_b2, p_tmp, 2048, DDIM);
        // write h2 directly into circular st slot t (st shift-append)
        glu_ln<<<BB, 256>>>(p_tmp, syn_l2s, syn_l2b, p_st + (size_t)t*DDIM, DDIM, MMM*DDIM);
        // NLM reads new st (base t+1), writes new at slot t
        nlm_kernel<<<dim3(DDIM/4, BB/32), 128>>>(nlm1_w, nlm1_b, nlm1_T,
                                                 nlm2_w, nlm2_b, nlm2_T,
                                                 (t + 1) & 31, t);
    }

    // 4) outputs
    synch_kernel<<<BB, 256>>>(outp + (size_t)2*BB*DDIM*MMM, NITR & 31);
    transpose_out<<<dim3(DDIM/32, BB, 2), 256>>>(outp, NITR & 31);
}

// round 8
// speedup vs baseline: 1.6330x; 1.2113x over previous
#include <cuda_runtime.h>
#include <cuda_bf16.h>
#include <math.h>

#define BB   256
#define OBSN 256
#define DIN  512
#define DDIM 1024
#define MMM  32
#define NSYN 64
#define NITR 4
#define NSYNCH 2080

// ---------------- fp32 scratch ----------------
__device__ float g_st[BB*MMM*DDIM];      // circular state trace [b][m][d]
__device__ float g_at[BB*MMM*DDIM];      // circular activated trace [b][m][d]
__device__ float g_tmp[BB*2048];         // GEMM outputs (pre-GLU)
__device__ float g_r[NSYNCH];
__device__ float g_invden[NSYNCH];
__device__ unsigned char g_done[BB];

// ---------------- packed bf16-pair (hi/lo) operand buffers ----------------
// activations: [m][KP] u32, KP = K/2
__device__ __align__(16) unsigned g_obsH[256*128],  g_obsL[256*128];
__device__ __align__(16) unsigned g_fH[256*256],    g_fL[256*256];
__device__ __align__(16) unsigned g_hH[256*512],    g_hL[256*512];
__device__ __align__(16) unsigned g_atH[256*512],   g_atL[256*512];
// weights transposed: [n][KP] u32
__device__ __align__(16) unsigned g_w1H[1024*128],  g_w1L[1024*128];
__device__ __align__(16) unsigned g_w2H[1024*256],  g_w2L[1024*256];
__device__ __align__(16) unsigned g_s1H[2048*768],  g_s1L[2048*768];
__device__ __align__(16) unsigned g_s2H[2048*512],  g_s2L[2048*512];

__device__ __forceinline__ float fsig(float x){ return __fdividef(1.f, 1.f + __expf(-x)); }

__device__ __forceinline__ unsigned pack2(__nv_bfloat16 a, __nv_bfloat16 b){
    return (unsigned)__bfloat16_as_ushort(a) | ((unsigned)__bfloat16_as_ushort(b) << 16);
}
__device__ __forceinline__ void split2(float x0, float x1, unsigned &hi, unsigned &lo){
    __nv_bfloat16 h0 = __float2bfloat16_rn(x0), h1 = __float2bfloat16_rn(x1);
    float r0 = x0 - __bfloat162float(h0);
    float r1 = x1 - __bfloat162float(h1);
    hi = pack2(h0, h1);
    lo = pack2(__float2bfloat16_rn(r0), __float2bfloat16_rn(r1));
}

// ---------------- mma / ldmatrix / cp.async primitives ----------------
__device__ __forceinline__ void mma16816(float* c, const unsigned* a, const unsigned* b){
    asm volatile("mma.sync.aligned.m16n8k16.row.col.f32.bf16.bf16.f32 "
        "{%0,%1,%2,%3},{%4,%5,%6,%7},{%8,%9},{%0,%1,%2,%3};"
        : "+f"(c[0]), "+f"(c[1]), "+f"(c[2]), "+f"(c[3])
        : "r"(a[0]), "r"(a[1]), "r"(a[2]), "r"(a[3]), "r"(b[0]), "r"(b[1]));
}
__device__ __forceinline__ void ldsm4(unsigned* r, unsigned saddr){
    asm volatile("ldmatrix.sync.aligned.m8n8.x4.shared.b16 {%0,%1,%2,%3}, [%4];"
        : "=r"(r[0]), "=r"(r[1]), "=r"(r[2]), "=r"(r[3]) : "r"(saddr));
}
__device__ __forceinline__ void cpasync16(unsigned sdst, const void* gsrc){
    asm volatile("cp.async.cg.shared.global [%0], [%1], 16;" :: "r"(sdst), "l"(gsrc));
}

// ---------------- decode dones (uint8 vs int32 vs float32 storage) ----------------
__global__ void decode_dones(const unsigned char* __restrict__ p)
{
    __shared__ int has_gt1, has_off;
    int t = threadIdx.x;
    if (t == 0){ has_gt1 = 0; has_off = 0; }
    __syncthreads();
    unsigned char v = p[t];
    if (v > 1)             atomicOr(&has_gt1, 1);
    if (v != 0 && (t & 3)) atomicOr(&has_off, 1);
    __syncthreads();
    bool d;
    if (has_gt1)      d = ((const float*)p)[t] != 0.0f;
    else if (has_off) d = p[t] != 0;
    else              d = ((const int*)p)[t] != 0;
    g_done[t] = d ? 1 : 0;
}

// ---------------- init: reset + transpose (B,D,M)->[b][m][d]; pack at-last ----------------
__global__ __launch_bounds__(256) void init_state(
    const float* __restrict__ st_in, const float* __restrict__ at_in,
    const float* __restrict__ st0,   const float* __restrict__ at0)
{
    __shared__ float ts[32][33], ta[32][33];
    int b = blockIdx.y, d0 = blockIdx.x*32, t = threadIdx.x;
    bool rs = g_done[b] != 0;
    #pragma unroll
    for (int i=0;i<4;i++){
        int idx = t + i*256; int dd = idx >> 5, m = idx & 31;
        int gidx = (d0+dd)*MMM + m;
        ts[dd][m] = rs ? st0[gidx] : st_in[(size_t)b*DDIM*MMM + gidx];
        ta[dd][m] = rs ? at0[gidx] : at_in[(size_t)b*DDIM*MMM + gidx];
    }
    __syncthreads();
    #pragma unroll
    for (int i=0;i<4;i++){
        int idx = t + i*256; int m = idx >> 5, dd = idx & 31;
        size_t o = ((size_t)b*MMM + m)*DDIM + d0 + dd;
        g_st[o] = ts[dd][m];
        g_at[o] = ta[dd][m];
        if (m == 31){
            // pack initial at-last column (logical last = phys 31 at base 0)
            float v = ta[dd][31];
            __nv_bfloat16 hb = __float2bfloat16_rn(v);
            float rl = v - __bfloat162float(hb);
            unsigned hs = __bfloat16_as_ushort(hb);
            unsigned ls = __bfloat16_as_ushort(__float2bfloat16_rn(rl));
            unsigned hp = __shfl_xor_sync(0xffffffffu, hs, 1);
            unsigned lp = __shfl_xor_sync(0xffffffffu, ls, 1);
            if ((dd & 1) == 0){
                size_t po = (size_t)b*(DDIM/2) + ((d0+dd)>>1);
                g_atH[po] = hs | (hp<<16);
                g_atL[po] = ls | (lp<<16);
            }
        }
    }
}

// ---------------- pack fp32 pairs -> bf16 hi/lo (obs pre-pass) ----------------
__global__ void pack_f32(const float* __restrict__ X, unsigned* __restrict__ H,
                         unsigned* __restrict__ L, int npair)
{
    int i = blockIdx.x*256 + threadIdx.x;
    if (i >= npair) return;
    unsigned h, l;
    split2(X[2*i], X[2*i+1], h, l);
    H[i] = h; L[i] = l;
}

// ---------------- weight transpose+convert: W[k][n] f32 -> Wt[n][kp] u32 hi/lo ----------
__global__ __launch_bounds__(256) void conv_wt_all(
    const float* __restrict__ w0, const float* __restrict__ w1,
    const float* __restrict__ w2, const float* __restrict__ w3)
{
    __shared__ float sm[32][33];
    int z = blockIdx.z;
    const float* W; unsigned *Th, *Tl; int K, N;
    if (z == 0){ W = w0; Th = g_w1H; Tl = g_w1L; K = 256;  N = 1024; }
    else if (z == 1){ W = w1; Th = g_w2H; Tl = g_w2L; K = 512;  N = 1024; }
    else if (z == 2){ W = w2; Th = g_s1H; Tl = g_s1L; K = 1536; N = 2048; }
    else { W = w3; Th = g_s2H; Tl = g_s2L; K = 1024; N = 2048; }
    int k0 = blockIdx.y*32, n0 = blockIdx.x*32;
    if (k0 >= K || n0 >= N) return;
    int t = threadIdx.x;
    int r = t >> 3, c = (t & 7)*4;
    float4 v = *(const float4*)(W + (size_t)(k0+r)*N + n0 + c);
    sm[r][c] = v.x; sm[r][c+1] = v.y; sm[r][c+2] = v.z; sm[r][c+3] = v.w;
    __syncthreads();
    int nr = t >> 3, kp2 = (t & 7)*2;   // 2 kp (4 k) per thread
    int kk = kp2*2;
    unsigned h0,l0,h1,l1;
    split2(sm[kk][nr],   sm[kk+1][nr], h0, l0);
    split2(sm[kk+2][nr], sm[kk+3][nr], h1, l1);
    int KP = K >> 1;
    size_t o = (size_t)(n0+nr)*KP + (k0>>1) + kp2;
    Th[o] = h0; Th[o+1] = h1;
    Tl[o] = l0; Tl[o+1] = l1;
}

// ---------------- 3xBF16 tensor GEMM, cp.async pipeline + ldmatrix ----------------
// C[256,N] = concat-A @ W + bias, A/B given as packed bf16 hi/lo pairs.
// BM=BN=64, BK=16 (8 kp), 3-stage cp.async, 256 thr = 8 warps (2m x 4n), warp 32x16.
#define GKP 12   // smem row stride (u32) for 8 kp + pad (conflict-free ldmatrix)
__global__ __launch_bounds__(256) void gemm_bf16p(
    const unsigned* __restrict__ A1h, const unsigned* __restrict__ A1l, int lda1,
    const unsigned* __restrict__ A2h, const unsigned* __restrict__ A2l, int lda2, int KP1,
    const unsigned* __restrict__ Bh,  const unsigned* __restrict__ Bl,  int ldb,
    const float* __restrict__ bias, float* __restrict__ C, int N, int KP)
{
    __shared__ unsigned As[3][2][64][GKP];
    __shared__ unsigned Bs[3][2][64][GKP];
    int tid = threadIdx.x;
    int m0 = blockIdx.y*64, n0 = blockIdx.x*64;
    unsigned aBase = (unsigned)__cvta_generic_to_shared(&As[0][0][0][0]);
    unsigned bBase = (unsigned)__cvta_generic_to_shared(&Bs[0][0][0][0]);

    // loader role: threads 0-127 -> A, 128-255 -> B; each does hi+lo 16B chunks
    bool isB = tid >= 128;
    int lt = tid & 127;
    int lrow = lt >> 1, lch = lt & 1;   // row 0..63, chunk 0/1 (kp offset 0/4)
    int KT = KP >> 3;

    // compute-side fragment addresses
    int wid = tid >> 5, lane = tid & 31;
    int wm = wid >> 2, wn = wid & 3;
    int arow = wm*32 + (lane & 7) + (lane & 8);
    int akp  = (lane & 16) ? 4 : 0;
    int brow = wn*16 + (lane & 7) + ((lane & 16) ? 8 : 0);
    int bkp  = (lane & 8) ? 4 : 0;
    unsigned aOff0 = ((unsigned)(arow   *GKP + akp))*4u;
    unsigned aOff1 = ((unsigned)((arow+16)*GKP + akp))*4u;
    unsigned bOff  = ((unsigned)(brow   *GKP + bkp))*4u;

    float acc[2][2][4];
    #pragma unroll
    for (int a=0;a<2;a++)
        #pragma unroll
        for (int b=0;b<2;b++)
            #pragma unroll
            for (int c=0;c<4;c++) acc[a][b][c]=0.f;

    auto issue = [&](int kt){
        if (kt < KT){
            int st = kt % 3;
            int kp0 = kt*8 + lch*4;
            unsigned dh = (((unsigned)(st*2+0)*64 + lrow)*GKP + lch*4)*4u;
            unsigned dl = (((unsigned)(st*2+1)*64 + lrow)*GKP + lch*4)*4u;
            if (!isB){
                const unsigned *sh_, *sl_;
                if (kp0 < KP1){
                    size_t o = (size_t)(m0+lrow)*lda1 + kp0;
                    sh_ = A1h + o; sl_ = A1l + o;
                } else {
                    size_t o = (size_t)(m0+lrow)*lda2 + (kp0 - KP1);
                    sh_ = A2h + o; sl_ = A2l + o;
                }
                cpasync16(aBase + dh, sh_);
                cpasync16(aBase + dl, sl_);
            } else {
                size_t o = (size_t)(n0+lrow)*ldb + kp0;
                cpasync16(bBase + dh, Bh + o);
                cpasync16(bBase + dl, Bl + o);
            }
        }
        asm volatile("cp.async.commit_group;" ::: "memory");
    };

    issue(0); issue(1);

    for (int kt = 0; kt < KT; kt++){
        asm volatile("cp.async.wait_group 1;" ::: "memory");
        __syncthreads();
        int st = kt % 3;
        unsigned sa = aBase + (unsigned)st*(2*64*GKP*4);
        unsigned sb = bBase + (unsigned)st*(2*64*GKP*4);
        unsigned ah0[4], ah1[4], al0[4], al1[4], bh[4], bl[4];
        ldsm4(ah0, sa + aOff0);
        ldsm4(ah1, sa + aOff1);
        ldsm4(al0, sa + (64*GKP*4) + aOff0);
        ldsm4(al1, sa + (64*GKP*4) + aOff1);
        ldsm4(bh,  sb + bOff);
        ldsm4(bl,  sb + (64*GKP*4) + bOff);

        mma16816(acc[0][0], ah0, bh+0);
        mma16816(acc[0][1], ah0, bh+2);
        mma16816(acc[1][0], ah1, bh+0);
        mma16816(acc[1][1], ah1, bh+2);
        mma16816(acc[0][0], ah0, bl+0);
        mma16816(acc[0][1], ah0, bl+2);
        mma16816(acc[1][0], ah1, bl+0);
        mma16816(acc[1][1], ah1, bl+2);
        mma16816(acc[0][0], al0, bh+0);
        mma16816(acc[0][1], al0, bh+2);
        mma16816(acc[1][0], al1, bh+0);
        mma16816(acc[1][1], al1, bh+2);

        issue(kt+2);
    }

    int g = lane >> 2, t4 = lane & 3;
    #pragma unroll
    for (int mt=0;mt<2;mt++){
        #pragma unroll
        for (int nt=0;nt<2;nt++){
            int row = m0 + wm*32 + mt*16 + g;
            int col = n0 + wn*16 + nt*8 + 2*t4;
            float bx = __ldg(bias + col), by = __ldg(bias + col + 1);
            float2 v0 = make_float2(acc[mt][nt][0]+bx, acc[mt][nt][1]+by);
            float2 v1 = make_float2(acc[mt][nt][2]+bx, acc[mt][nt][3]+by);
            *(float2*)&C[(size_t)row*N + col]     = v0;
            *(float2*)&C[(size_t)(row+8)*N + col] = v1;
        }
    }
}

// ---------------- GLU + LayerNorm -> packed bf16 hi/lo ----------------
__global__ __launch_bounds__(256) void glu_ln_pack(
    const float* __restrict__ X, const float* __restrict__ gamma,
    const float* __restrict__ beta, unsigned* __restrict__ outH,
    unsigned* __restrict__ outL, int N)
{
    __shared__ float sg[1024];
    __shared__ float red[18];
    int b = blockIdx.x, t = threadIdx.x;
    const float* xr = X + (size_t)b*2*N;
    int NP = N >> 1;
    float s1=0.f, s2=0.f;
    for (int p=t; p<NP; p+=256){
        float2 a = *(const float2*)(xr + 2*p);
        float2 c = *(const float2*)(xr + N + 2*p);
        float g0 = a.x * fsig(c.x), g1 = a.y * fsig(c.y);
        sg[2*p] = g0; sg[2*p+1] = g1;
        s1 += g0+g1; s2 += g0*g0 + g1*g1;
    }
    #pragma unroll
    for (int o=16;o;o>>=1){ s1+=__shfl_xor_sync(0xffffffffu,s1,o); s2+=__shfl_xor_sync(0xffffffffu,s2,o); }
    if ((t&31)==0){ red[t>>5]=s1; red[8+(t>>5)]=s2; }
    __syncthreads();
    if (t==0){
        float a=0.f,c=0.f;
        for (int i=0;i<8;i++){ a+=red[i]; c+=red[8+i]; }
        red[16]=a; red[17]=c;
    }
    __syncthreads();
    float mu  = red[16]/(float)N;
    float var = red[17]/(float)N - mu*mu;
    float inv = rsqrtf(var + 1e-6f);
    for (int p=t; p<NP; p+=256){
        int j = 2*p;
        float y0 = (sg[j]  -mu)*inv*gamma[j]   + beta[j];
        float y1 = (sg[j+1]-mu)*inv*gamma[j+1] + beta[j+1];
        unsigned h, l;
        split2(y0, y1, h, l);
        outH[(size_t)b*NP + p] = h;
        outL[(size_t)b*NP + p] = l;
    }
}

// ---------------- GLU + LayerNorm -> fp32 (st slot) ----------------
__global__ __launch_bounds__(256) void glu_ln_f32(
    const float* __restrict__ X, const float* __restrict__ gamma,
    const float* __restrict__ beta, float* __restrict__ outp, int N, int ostride)
{
    __shared__ float sg[1024];
    __shared__ float red[18];
    int b = blockIdx.x, t = threadIdx.x;
    const float* xr = X + (size_t)b*2*N;
    float s1=0.f, s2=0.f;
    for (int j=t; j<N; j+=256){
        float a = xr[j];
        float gl = a * fsig(xr[N+j]);
        sg[j]=gl; s1+=gl; s2+=gl*gl;
    }
    #pragma unroll
    for (int o=16;o;o>>=1){ s1+=__shfl_xor_sync(0xffffffffu,s1,o); s2+=__shfl_xor_sync(0xffffffffu,s2,o); }
    if ((t&31)==0){ red[t>>5]=s1; red[8+(t>>5)]=s2; }
    __syncthreads();
    if (t==0){
        float a=0.f,c=0.f;
        for (int i=0;i<8;i++){ a+=red[i]; c+=red[8+i]; }
        red[16]=a; red[17]=c;
    }
    __syncthreads();
    float mu  = red[16]/(float)N;
    float var = red[17]/(float)N - mu*mu;
    float inv = rsqrtf(var + 1e-6f);
    for (int j=t; j<N; j+=256)
        outp[(size_t)b*ostride + j] = (sg[j]-mu)*inv*gamma[j] + beta[j];
}

// ---------------- NLM: per-(b,d) 32->32 GLU MLP -> 16->2 GLU -> scalar ----------------
__global__ __launch_bounds__(128) void nlm_kernel(
    const float* __restrict__ w1, const float* __restrict__ b1, const float* __restrict__ T1,
    const float* __restrict__ w2, const float* __restrict__ b2, const float* __restrict__ T2,
    int base, int slot)
{
    __shared__ float W1s[32*32*4];
    __shared__ float STs[32*32*4];
    __shared__ float B1s[32*4];
    __shared__ float W2s[32*4];
    __shared__ float B2s[8];
    int t = threadIdx.x;
    int d0 = blockIdx.x*4, b0 = blockIdx.y*32;

    #pragma unroll
    for (int i=0;i<8;i++){
        int idx = t + i*128;
        float4 v = *(const float4*)(w1 + (size_t)idx*DDIM + d0);
        *(float4*)&W1s[idx*4] = v;
        int bb = idx >> 5, m = idx & 31;
        int phys = (base + m) & 31;
        float4 s = *(const float4*)(g_st + ((size_t)(b0+bb)*MMM + phys)*DDIM + d0);
        *(float4*)&STs[(m*32+bb)*4] = s;
    }
    { int h = t>>2, dd = t&3; B1s[t] = b1[(d0+dd)*32 + h]; }
    { int kj = t>>2, dd = t&3; W2s[t] = w2[(size_t)kj*DDIM + d0 + dd]; }
    if (t < 8){ int j = t>>2, dd = t&3; B2s[t] = b2[(d0+dd)*2 + j]; }
    __syncthreads();

    float invT1 = 1.0f/T1[0], invT2 = 1.0f/T2[0];
    int dd = t & 3;
    int bb = t >> 2;

    float str[32];
    #pragma unroll
    for (int m=0;m<32;m++) str[m] = STs[m*128 + t];

    float x[32];
    #pragma unroll
    for (int h=0;h<32;h++){
        float acc = B1s[h*4+dd];
        #pragma unroll
        for (int m=0;m<32;m++) acc += str[m]*W1s[(m*32+h)*4+dd];
        x[h] = acc*invT1;
    }
    float y0 = B2s[dd], y1 = B2s[4+dd];
    #pragma unroll
    for (int k=0;k<16;k++){
        float gl = x[k] * fsig(x[k+16]);
        y0 += gl*W2s[(k*2+0)*4+dd];
        y1 += gl*W2s[(k*2+1)*4+dd];
    }
    y0 *= invT2; y1 *= invT2;
    float outv = y0 * fsig(y1);
    g_at[((size_t)(b0+bb)*MMM + slot)*DDIM + d0 + dd] = outv;

    // packed bf16 hi/lo of the new at-last column for next iteration's syn1 GEMM
    __nv_bfloat16 hb = __float2bfloat16_rn(outv);
    float rl = outv - __bfloat162float(hb);
    unsigned hs = __bfloat16_as_ushort(hb);
    unsigned ls = __bfloat16_as_ushort(__float2bfloat16_rn(rl));
    unsigned hp = __shfl_xor_sync(0xffffffffu, hs, 1);
    unsigned lp = __shfl_xor_sync(0xffffffffu, ls, 1);
    if ((dd & 1) == 0){
        size_t po = (size_t)(b0+bb)*(DDIM/2) + ((d0+dd)>>1);
        g_atH[po] = hs | (hp<<16);
        g_atL[po] = ls | (lp<<16);
    }
}

// ---------------- synch prep + main ----------------
__global__ void synch_prep(const float* __restrict__ dp)
{
    int p = blockIdx.x*256 + threadIdx.x;
    if (p >= NSYNCH) return;
    float c = fminf(fmaxf(dp[p], 0.f), 4.f);
    float r = __expf(-c);
    float den = 1.f, rp = 1.f;
    #pragma unroll
    for (int k=1;k<32;k++){ rp *= r; den += rp; }
    g_r[p] = r;
    g_invden[p] = rsqrtf(den);
}

__global__ __launch_bounds__(256) void synch_kernel(float* __restrict__ outp, int base)
{
    __shared__ float S[32][64];
    int b = blockIdx.x, t = threadIdx.x;
    #pragma unroll
    for (int i=0;i<8;i++){
        int idx = t + i*256; int m = idx >> 6, n = idx & 63;
        S[m][n] = g_at[((size_t)b*MMM + ((base+m)&31))*DDIM + (DDIM-NSYN) + n];
    }
    __syncthreads();
    for (int p=t; p<NSYNCH; p+=256){
        int i=0, off=0;
        while (p >= off + (NSYN - i)){ off += NSYN - i; ++i; }
        int j = i + (p - off);
        float r = g_r[p];
        float num = 0.f;
        #pragma unroll
        for (int m=0;m<32;m++)
            num = num*r + S[m][i]*S[m][j];
        outp[(size_t)b*NSYNCH + p] = num * g_invden[p];
    }
}

// ---------------- final transpose [b][m][d] -> (B,D,M) ----------------
__global__ void transpose_out(float* __restrict__ outp, int base)
{
    __shared__ float tile[32][33];
    const float* src = blockIdx.z ? g_at : g_st;
    float* dst = outp + (size_t)blockIdx.z * (size_t)BB*DDIM*MMM;
    int b = blockIdx.y, d0 = blockIdx.x*32, t = threadIdx.x;
    #pragma unroll
    for (int i=0;i<4;i++){
        int idx = t + i*256; int m = idx >> 5, dd = idx & 31;
        tile[m][dd] = src[((size_t)b*MMM + ((base+m)&31))*DDIM + d0 + dd];
    }
    __syncthreads();
    #pragma unroll
    for (int i=0;i<4;i++){
        int idx = t + i*256; int dd = idx >> 5, m = idx & 31;
        dst[((size_t)b*DDIM + d0 + dd)*MMM + m] = tile[m][dd];
    }
}

// ---------------- host launch ----------------
extern "C" void kernel_launch(void* const* d_in, const int* in_sizes, int n_in,
                              void* d_out, int out_size)
{
    const float* obs          = (const float*)d_in[0];
    const unsigned char* dones= (const unsigned char*)d_in[1];
    const float* state_trace  = (const float*)d_in[3];
    const float* at_trace     = (const float*)d_in[4];
    const float* start_trace  = (const float*)d_in[5];
    const float* start_at     = (const float*)d_in[6];
    const float* bb_w1  = (const float*)d_in[7];
    const float* bb_b1  = (const float*)d_in[8];
    const float* bb_l1s = (const float*)d_in[9];
    const float* bb_l1b = (const float*)d_in[10];
    const float* bb_w2  = (const float*)d_in[11];
    const float* bb_b2  = (const float*)d_in[12];
    const float* bb_l2s = (const float*)d_in[13];
    const float* bb_l2b = (const float*)d_in[14];
    const float* syn_w1 = (const float*)d_in[15];
    const float* syn_b1 = (const float*)d_in[16];
    const float* syn_l1s= (const float*)d_in[17];
    const float* syn_l1b= (const float*)d_in[18];
    const float* syn_w2 = (const float*)d_in[19];
    const float* syn_b2 = (const float*)d_in[20];
    const float* syn_l2s= (const float*)d_in[21];
    const float* syn_l2b= (const float*)d_in[22];
    const float* nlm1_w = (const float*)d_in[23];
    const float* nlm1_b = (const float*)d_in[24];
    const float* nlm1_T = (const float*)d_in[25];
    const float* nlm2_w = (const float*)d_in[26];
    const float* nlm2_b = (const float*)d_in[27];
    const float* nlm2_T = (const float*)d_in[28];
    const float* decayp = (const float*)d_in[29];
    float* outp = (float*)d_out;

    float *p_tmp, *p_st;
    unsigned *p_obsH,*p_obsL,*p_fH,*p_fL,*p_hH,*p_hL,*p_atH,*p_atL;
    unsigned *p_w1H,*p_w1L,*p_w2H,*p_w2L,*p_s1H,*p_s1L,*p_s2H,*p_s2L;
    cudaGetSymbolAddress((void**)&p_tmp, g_tmp);
    cudaGetSymbolAddress((void**)&p_st,  g_st);
    cudaGetSymbolAddress((void**)&p_obsH, g_obsH); cudaGetSymbolAddress((void**)&p_obsL, g_obsL);
    cudaGetSymbolAddress((void**)&p_fH,   g_fH);   cudaGetSymbolAddress((void**)&p_fL,   g_fL);
    cudaGetSymbolAddress((void**)&p_hH,   g_hH);   cudaGetSymbolAddress((void**)&p_hL,   g_hL);
    cudaGetSymbolAddress((void**)&p_atH,  g_atH);  cudaGetSymbolAddress((void**)&p_atL,  g_atL);
    cudaGetSymbolAddress((void**)&p_w1H,  g_w1H);  cudaGetSymbolAddress((void**)&p_w1L,  g_w1L);
    cudaGetSymbolAddress((void**)&p_w2H,  g_w2H);  cudaGetSymbolAddress((void**)&p_w2L,  g_w2L);
    cudaGetSymbolAddress((void**)&p_s1H,  g_s1H);  cudaGetSymbolAddress((void**)&p_s1L,  g_s1L);
    cudaGetSymbolAddress((void**)&p_s2H,  g_s2H);  cudaGetSymbolAddress((void**)&p_s2L,  g_s2L);

    // 1) flags, state relayout (+at-last pack), synch prefactors, operand conversion
    decode_dones<<<1, BB>>>(dones);
    init_state<<<dim3(DDIM/32, BB), 256>>>(state_trace, at_trace, start_trace, start_at);
    synch_prep<<<(NSYNCH+255)/256, 256>>>(decayp);
    pack_f32<<<(BB*OBSN/2 + 255)/256, 256>>>(obs, p_obsH, p_obsL, BB*OBSN/2);
    conv_wt_all<<<dim3(2048/32, 1536/32, 4), 256>>>(bb_w1, bb_w2, syn_w1, syn_w2);

    // 2) backbone
    gemm_bf16p<<<dim3(16, 4), 256>>>(p_obsH, p_obsL, 128,
                                     p_obsH, p_obsL, 128, 128,
                                     p_w1H, p_w1L, 128,
                                     bb_b1, p_tmp, 1024, 128);
    glu_ln_pack<<<BB, 256>>>(p_tmp, bb_l1s, bb_l1b, p_fH, p_fL, DIN);
    gemm_bf16p<<<dim3(16, 4), 256>>>(p_fH, p_fL, 256,
                                     p_fH, p_fL, 256, 256,
                                     p_w2H, p_w2L, 256,
                                     bb_b2, p_tmp, 1024, 256);
    glu_ln_pack<<<BB, 256>>>(p_tmp, bb_l2s, bb_l2b, p_fH, p_fL, DIN);

    // 3) recurrent iterations
    for (int t = 0; t < NITR; t++){
        // syn1: A = concat(f, at_last) packed; KP1 = 256 (f part)
        gemm_bf16p<<<dim3(32, 4), 256>>>(p_fH, p_fL, 256,
                                         p_atH, p_atL, 512, 256,
                                         p_s1H, p_s1L, 768,
                                         syn_b1, p_tmp, 2048, 768);
        glu_ln_pack<<<BB, 256>>>(p_tmp, syn_l1s, syn_l1b, p_hH, p_hL, DDIM);
        gemm_bf16p<<<dim3(32, 4), 256>>>(p_hH, p_hL, 512,
                                         p_hH, p_hL, 512, 512,
                                         p_s2H, p_s2L, 512,
                                         syn_b2, p_tmp, 2048, 512);
        glu_ln_f32<<<BB, 256>>>(p_tmp, syn_l2s, syn_l2b, p_st + (size_t)t*DDIM, DDIM, MMM*DDIM);
        nlm_kernel<<<dim3(DDIM/4, BB/32), 128>>>(nlm1_w, nlm1_b, nlm1_T,
                                                 nlm2_w, nlm2_b, nlm2_T,
                                                 (t + 1) & 31, t);
    }

    // 4) outputs
    synch_kernel<<<BB, 256>>>(outp + (size_t)2*BB*DDIM*MMM, NITR & 31);
    transpose_out<<<dim3(DDIM/32, BB, 2), 256>>>(outp, NITR & 31);
}